// round 1
// baseline (speedup 1.0000x reference)
#include <cuda_runtime.h>

#define NROWS 16384   // B*M*P = 8*4*512
#define HID   768
#define NH    12
#define HS    64
#define PSEQ  512

// Scratch (allocation-free rule: __device__ globals)
__device__ float g_q[NROWS * HID];
__device__ float g_k[NROWS * HID];
__device__ float g_v[NROWS * HID];
__device__ float g_ctx[NROWS * HID];

// ---------------------------------------------------------------------------
// C[Nrows, Ncols] = A[Nrows, K] @ W[K, Ncols] + bias
// 128x128 tile, TK=8, 256 threads, 8x8 micro-tile
// ---------------------------------------------------------------------------
__global__ __launch_bounds__(256) void gemm_bias(
    const float* __restrict__ A, const float* __restrict__ W,
    const float* __restrict__ bias, float* __restrict__ C,
    int Nrows, int K, int Ncols)
{
    __shared__ float As[8][128];
    __shared__ float Bs[8][128];

    const int bm = blockIdx.y * 128;
    const int bn = blockIdx.x * 128;
    const int tid = threadIdx.x;
    const int tx = tid & 15;
    const int ty = tid >> 4;

    const int arow = tid >> 1;         // 0..127
    const int acol = (tid & 1) * 4;    // 0 or 4
    const int brow = tid >> 5;         // 0..7
    const int bcol = (tid & 31) * 4;   // 0..124

    float acc[8][8];
#pragma unroll
    for (int i = 0; i < 8; i++)
#pragma unroll
        for (int j = 0; j < 8; j++) acc[i][j] = 0.f;

    for (int k0 = 0; k0 < K; k0 += 8) {
        float4 av = *(const float4*)(A + (size_t)(bm + arow) * K + k0 + acol);
        As[acol + 0][arow] = av.x;
        As[acol + 1][arow] = av.y;
        As[acol + 2][arow] = av.z;
        As[acol + 3][arow] = av.w;
        float4 wv = *(const float4*)(W + (size_t)(k0 + brow) * Ncols + bn + bcol);
        *(float4*)&Bs[brow][bcol] = wv;
        __syncthreads();

#pragma unroll
        for (int kk = 0; kk < 8; kk++) {
            float4 a0 = *(float4*)&As[kk][ty * 4];
            float4 a1 = *(float4*)&As[kk][ty * 4 + 64];
            float4 b0 = *(float4*)&Bs[kk][tx * 4];
            float4 b1 = *(float4*)&Bs[kk][tx * 4 + 64];
            float ar[8] = {a0.x, a0.y, a0.z, a0.w, a1.x, a1.y, a1.z, a1.w};
            float br[8] = {b0.x, b0.y, b0.z, b0.w, b1.x, b1.y, b1.z, b1.w};
#pragma unroll
            for (int i = 0; i < 8; i++)
#pragma unroll
                for (int j = 0; j < 8; j++)
                    acc[i][j] = fmaf(ar[i], br[j], acc[i][j]);
        }
        __syncthreads();
    }

#pragma unroll
    for (int i = 0; i < 8; i++) {
        int r = bm + ((i < 4) ? (ty * 4 + i) : (64 + ty * 4 + i - 4));
#pragma unroll
        for (int j = 0; j < 8; j++) {
            int c = bn + ((j < 4) ? (tx * 4 + j) : (64 + tx * 4 + j - 4));
            C[(size_t)r * Ncols + c] = acc[i][j] + bias[c];
        }
    }
}

// ---------------------------------------------------------------------------
// Flash attention: per (b*m, head) over P=512 patches, head dim 64.
// Block = 64 q-rows; KV tiles of 32 rows; online softmax.
// grid = (P/64, NH, B*M), 256 threads (16x16).
// ---------------------------------------------------------------------------
#define KP_STRIDE_K 72   // K tile rows [32][72]
#define KP_STRIDE_P 36   // P tile rows [64][36] (same buffer)

__global__ __launch_bounds__(256) void flash_attn(
    const float* __restrict__ Q, const float* __restrict__ K,
    const float* __restrict__ V, float* __restrict__ O)
{
    __shared__ float Qs[64][64];
    __shared__ float kp[32 * KP_STRIDE_K];   // aliased: K [32][72] then P [64][36]
    __shared__ float Vs[32][64];

    const int tid = threadIdx.x;
    const int tx = tid & 15;
    const int ty = tid >> 4;
    const int q0 = blockIdx.x * 64;
    const int head = blockIdx.y;
    const int bm = blockIdx.z;
    const size_t rowbase = (size_t)bm * PSEQ;
    const int colbase = head * HS;

    // Load 64x64 Q tile
    {
        int r = tid & 63;
        int c0 = (tid >> 6) * 16;
        const float* src = Q + (rowbase + q0 + r) * HID + colbase + c0;
#pragma unroll
        for (int u = 0; u < 4; u++)
            *(float4*)&Qs[r][c0 + u * 4] = *(const float4*)(src + u * 4);
    }

    float m[4], l[4], oacc[4][4];
#pragma unroll
    for (int i = 0; i < 4; i++) {
        m[i] = -1e30f;
        l[i] = 0.f;
#pragma unroll
        for (int j = 0; j < 4; j++) oacc[i][j] = 0.f;
    }
    __syncthreads();

    for (int n0 = 0; n0 < PSEQ; n0 += 32) {
        // Load K,V 32x64 tiles
        {
            int r = tid & 31;
            int c0 = (tid >> 5) * 8;
            const float* ksrc = K + (rowbase + n0 + r) * HID + colbase + c0;
            const float* vsrc = V + (rowbase + n0 + r) * HID + colbase + c0;
#pragma unroll
            for (int u = 0; u < 2; u++) {
                *(float4*)&kp[r * KP_STRIDE_K + c0 + u * 4] = *(const float4*)(ksrc + u * 4);
                *(float4*)&Vs[r][c0 + u * 4] = *(const float4*)(vsrc + u * 4);
            }
        }
        __syncthreads();

        // S = (Q K^T) * 1/sqrt(64); thread owns 4 rows x 2 cols
        float s[4][2];
#pragma unroll
        for (int i = 0; i < 4; i++) { s[i][0] = 0.f; s[i][1] = 0.f; }
        const float* kb0 = &kp[(tx * 2 + 0) * KP_STRIDE_K];
        const float* kb1 = &kp[(tx * 2 + 1) * KP_STRIDE_K];
#pragma unroll 8
        for (int d = 0; d < 64; d++) {
            float b0 = kb0[d];
            float b1 = kb1[d];
            float a0 = Qs[ty * 4 + 0][d];
            float a1 = Qs[ty * 4 + 1][d];
            float a2 = Qs[ty * 4 + 2][d];
            float a3 = Qs[ty * 4 + 3][d];
            s[0][0] = fmaf(a0, b0, s[0][0]); s[0][1] = fmaf(a0, b1, s[0][1]);
            s[1][0] = fmaf(a1, b0, s[1][0]); s[1][1] = fmaf(a1, b1, s[1][1]);
            s[2][0] = fmaf(a2, b0, s[2][0]); s[2][1] = fmaf(a2, b1, s[2][1]);
            s[3][0] = fmaf(a3, b0, s[3][0]); s[3][1] = fmaf(a3, b1, s[3][1]);
        }

        // Online softmax update (rows reduced across the 16 tx-lanes)
        float p[4][2];
#pragma unroll
        for (int i = 0; i < 4; i++) {
            s[i][0] *= 0.125f;
            s[i][1] *= 0.125f;
            float rmax = fmaxf(s[i][0], s[i][1]);
#pragma unroll
            for (int off = 8; off >= 1; off >>= 1)
                rmax = fmaxf(rmax, __shfl_xor_sync(0xffffffffu, rmax, off, 16));
            float mnew = fmaxf(m[i], rmax);
            float alpha = __expf(m[i] - mnew);
            p[i][0] = __expf(s[i][0] - mnew);
            p[i][1] = __expf(s[i][1] - mnew);
            float rsum = p[i][0] + p[i][1];
#pragma unroll
            for (int off = 8; off >= 1; off >>= 1)
                rsum += __shfl_xor_sync(0xffffffffu, rsum, off, 16);
            l[i] = l[i] * alpha + rsum;
            m[i] = mnew;
#pragma unroll
            for (int j = 0; j < 4; j++) oacc[i][j] *= alpha;
        }
        __syncthreads();  // all threads done reading kp as K

        // Write P into kp as [64][36]
#pragma unroll
        for (int i = 0; i < 4; i++) {
            kp[(ty * 4 + i) * KP_STRIDE_P + tx * 2 + 0] = p[i][0];
            kp[(ty * 4 + i) * KP_STRIDE_P + tx * 2 + 1] = p[i][1];
        }
        __syncthreads();

        // O += P @ V  (reduce over 32 kv rows)
#pragma unroll 4
        for (int n = 0; n < 32; n++) {
            float4 b = *(float4*)&Vs[n][tx * 4];
            float a0 = kp[(ty * 4 + 0) * KP_STRIDE_P + n];
            float a1 = kp[(ty * 4 + 1) * KP_STRIDE_P + n];
            float a2 = kp[(ty * 4 + 2) * KP_STRIDE_P + n];
            float a3 = kp[(ty * 4 + 3) * KP_STRIDE_P + n];
            oacc[0][0] = fmaf(a0, b.x, oacc[0][0]); oacc[0][1] = fmaf(a0, b.y, oacc[0][1]);
            oacc[0][2] = fmaf(a0, b.z, oacc[0][2]); oacc[0][3] = fmaf(a0, b.w, oacc[0][3]);
            oacc[1][0] = fmaf(a1, b.x, oacc[1][0]); oacc[1][1] = fmaf(a1, b.y, oacc[1][1]);
            oacc[1][2] = fmaf(a1, b.z, oacc[1][2]); oacc[1][3] = fmaf(a1, b.w, oacc[1][3]);
            oacc[2][0] = fmaf(a2, b.x, oacc[2][0]); oacc[2][1] = fmaf(a2, b.y, oacc[2][1]);
            oacc[2][2] = fmaf(a2, b.z, oacc[2][2]); oacc[2][3] = fmaf(a2, b.w, oacc[2][3]);
            oacc[3][0] = fmaf(a3, b.x, oacc[3][0]); oacc[3][1] = fmaf(a3, b.y, oacc[3][1]);
            oacc[3][2] = fmaf(a3, b.z, oacc[3][2]); oacc[3][3] = fmaf(a3, b.w, oacc[3][3]);
        }
        __syncthreads();  // done with kp/Vs before next tile load
    }

    // Normalize and write ctx: row = rowbase+q0+row, col = head*64 + d
#pragma unroll
    for (int i = 0; i < 4; i++) {
        float inv = 1.0f / l[i];
        size_t r = rowbase + q0 + ty * 4 + i;
#pragma unroll
        for (int j = 0; j < 4; j++)
            O[r * HID + colbase + tx * 4 + j] = oacc[i][j] * inv;
    }
}

// ---------------------------------------------------------------------------
extern "C" void kernel_launch(void* const* d_in, const int* in_sizes, int n_in,
                              void* d_out, int out_size)
{
    const float* X  = (const float*)d_in[0];
    const float* Wq = (const float*)d_in[1];
    const float* bq = (const float*)d_in[2];
    const float* Wk = (const float*)d_in[3];
    const float* bk = (const float*)d_in[4];
    const float* Wv = (const float*)d_in[5];
    const float* bv = (const float*)d_in[6];
    const float* Wo = (const float*)d_in[7];
    const float* bo = (const float*)d_in[8];
    float* out = (float*)d_out;

    static float *pq = nullptr, *pk = nullptr, *pv = nullptr, *pctx = nullptr;
    if (!pq) {
        cudaGetSymbolAddress((void**)&pq, g_q);
        cudaGetSymbolAddress((void**)&pk, g_k);
        cudaGetSymbolAddress((void**)&pv, g_v);
        cudaGetSymbolAddress((void**)&pctx, g_ctx);
    }

    dim3 gproj(HID / 128, NROWS / 128);   // (6, 128)
    gemm_bias<<<gproj, 256>>>(X, Wq, bq, pq, NROWS, HID, HID);
    gemm_bias<<<gproj, 256>>>(X, Wk, bk, pk, NROWS, HID, HID);
    gemm_bias<<<gproj, 256>>>(X, Wv, bv, pv, NROWS, HID, HID);

    dim3 gattn(PSEQ / 64, NH, NROWS / PSEQ);  // (8, 12, 32)
    flash_attn<<<gattn, 256>>>(pq, pk, pv, pctx);

    gemm_bias<<<gproj, 256>>>(pctx, Wo, bo, out, NROWS, HID, HID);
}

// round 3
// speedup vs baseline: 3.6038x; 3.6038x over previous
#include <cuda_runtime.h>
#include <cstdint>

#define NROWS 16384   // B*M*P = 8*4*512
#define HID   768
#define NH    12
#define HS    64
#define PSEQ  512

// Scratch (allocation-free rule: __device__ globals)
__device__ float g_q[NROWS * HID];
__device__ float g_k[NROWS * HID];
__device__ float g_v[NROWS * HID];
__device__ float g_ctx[NROWS * HID];

// ---------------------------------------------------------------------------
// helpers
// ---------------------------------------------------------------------------
__device__ __forceinline__ uint32_t f2tf32(float f) {
    uint32_t r;
    asm("cvt.rna.tf32.f32 %0, %1;" : "=r"(r) : "f"(f));
    return r;
}

// D += A*B, m16n8k8 tf32 (row.col)
#define MMA_TF32(d, a, b0, b1) \
    asm volatile("mma.sync.aligned.m16n8k8.row.col.f32.tf32.tf32.f32 " \
        "{%0,%1,%2,%3}, {%4,%5,%6,%7}, {%8,%9}, {%0,%1,%2,%3};" \
        : "+f"((d)[0]), "+f"((d)[1]), "+f"((d)[2]), "+f"((d)[3]) \
        : "r"((a)[0]), "r"((a)[1]), "r"((a)[2]), "r"((a)[3]), "r"(b0), "r"(b1))

// ===========================================================================
// GEMM: C[16384,768] = A @ W + bias  via mma.sync tf32
// tile 128x128x32, 256 threads = 8 warps (2 x 4), warp tile 64x32
// As[m][k] stride 36, Bs[k][n] stride 132 (both conflict-free for frag LDS)
// ===========================================================================
#define AS_STRIDE 36
#define BS_STRIDE 132

__global__ __launch_bounds__(256) void gemm_mma(
    const float* __restrict__ A, const float* __restrict__ W,
    const float* __restrict__ bias, float* __restrict__ C)
{
    __shared__ uint32_t As[128 * AS_STRIDE];   // 18432 B
    __shared__ uint32_t Bs[32 * BS_STRIDE];    // 16896 B

    const int tid = threadIdx.x;
    const int wid = tid >> 5;
    const int lane = tid & 31;
    const int gid = lane >> 2;     // 0..7
    const int tig = lane & 3;      // 0..3
    const int wm = wid >> 2;       // 0..1  -> 64 rows
    const int wn = wid & 3;        // 0..3  -> 32 cols
    const int bm = blockIdx.y * 128;
    const int bn = blockIdx.x * 128;

    float acc[4][4][4] = {};

    for (int k0 = 0; k0 < HID; k0 += 32) {
        __syncthreads();
        // A tile: 128 x 32
#pragma unroll
        for (int u = 0; u < 4; u++) {
            int idx = u * 256 + tid;
            int r = idx >> 3, c4 = idx & 7;
            float4 v = *(const float4*)(A + (size_t)(bm + r) * HID + k0 + c4 * 4);
            uint32_t* d = &As[r * AS_STRIDE + c4 * 4];
            *(uint4*)d = make_uint4(f2tf32(v.x), f2tf32(v.y), f2tf32(v.z), f2tf32(v.w));
        }
        // B tile: W[k0..k0+31][bn..bn+127], kept [k][n]
#pragma unroll
        for (int u = 0; u < 4; u++) {
            int idx = u * 256 + tid;
            int kr = idx >> 5, nc = idx & 31;
            float4 v = *(const float4*)(W + (size_t)(k0 + kr) * HID + bn + nc * 4);
            uint32_t* d = &Bs[kr * BS_STRIDE + nc * 4];
            *(uint4*)d = make_uint4(f2tf32(v.x), f2tf32(v.y), f2tf32(v.z), f2tf32(v.w));
        }
        __syncthreads();

#pragma unroll
        for (int ks = 0; ks < 4; ks++) {
            uint32_t a[4][4];
#pragma unroll
            for (int mt = 0; mt < 4; mt++) {
                const uint32_t* p = &As[(wm * 64 + mt * 16 + gid) * AS_STRIDE + ks * 8 + tig];
                a[mt][0] = p[0];
                a[mt][1] = p[8 * AS_STRIDE];
                a[mt][2] = p[4];
                a[mt][3] = p[8 * AS_STRIDE + 4];
            }
#pragma unroll
            for (int nt = 0; nt < 4; nt++) {
                const uint32_t* p = &Bs[(ks * 8 + tig) * BS_STRIDE + wn * 32 + nt * 8 + gid];
                uint32_t b0 = p[0];
                uint32_t b1 = p[4 * BS_STRIDE];
#pragma unroll
                for (int mt = 0; mt < 4; mt++)
                    MMA_TF32(acc[mt][nt], a[mt], b0, b1);
            }
        }
    }

    // epilogue
#pragma unroll
    for (int mt = 0; mt < 4; mt++) {
        int r0 = bm + wm * 64 + mt * 16 + gid;
#pragma unroll
        for (int nt = 0; nt < 4; nt++) {
            int c = bn + wn * 32 + nt * 8 + tig * 2;
            float b0 = bias[c], b1 = bias[c + 1];
            float2 o0 = {acc[mt][nt][0] + b0, acc[mt][nt][1] + b1};
            float2 o1 = {acc[mt][nt][2] + b0, acc[mt][nt][3] + b1};
            *(float2*)(C + (size_t)r0 * HID + c) = o0;
            *(float2*)(C + (size_t)(r0 + 8) * HID + c) = o1;
        }
    }
}

// ===========================================================================
// Flash attention with mma.sync tf32.
// Block = 128 thr (4 warps), q-tile 64 (warp owns 16 q-rows), KV tiles of 64.
// Q frags in registers; softmax fully in registers (shfl over 4 lanes/row);
// P round-trips through smem (aliases K buffer).
// ===========================================================================
#define FS_STRIDE 68   // 64 + 4 pad

__global__ __launch_bounds__(128) void flash_mma(
    const float* __restrict__ Q, const float* __restrict__ K,
    const float* __restrict__ V, float* __restrict__ O)
{
    __shared__ uint32_t KPs[64 * FS_STRIDE];   // K tile / P tile (aliased)
    __shared__ uint32_t Vs[64 * FS_STRIDE];

    const int tid = threadIdx.x;
    const int wid = tid >> 5;     // 0..3 : q-row group
    const int lane = tid & 31;
    const int gid = lane >> 2;
    const int tig = lane & 3;
    const int q0 = blockIdx.x * 64;
    const int head = blockIdx.y;
    const int bmi = blockIdx.z;
    const size_t rowbase = (size_t)bmi * PSEQ;
    const int colbase = head * HS;

    // ---- load Q tile (64x64) into KPs, then lift to register fragments
#pragma unroll
    for (int u = 0; u < 8; u++) {
        int idx = u * 128 + tid;
        int r = idx >> 4, c4 = idx & 15;
        float4 v = *(const float4*)(Q + (rowbase + q0 + r) * HID + colbase + c4 * 4);
        uint32_t* d = &KPs[r * FS_STRIDE + c4 * 4];
        *(uint4*)d = make_uint4(f2tf32(v.x), f2tf32(v.y), f2tf32(v.z), f2tf32(v.w));
    }
    __syncthreads();
    uint32_t qf[8][4];
#pragma unroll
    for (int ks = 0; ks < 8; ks++) {
        const uint32_t* p = &KPs[(wid * 16 + gid) * FS_STRIDE + ks * 8 + tig];
        qf[ks][0] = p[0];
        qf[ks][1] = p[8 * FS_STRIDE];
        qf[ks][2] = p[4];
        qf[ks][3] = p[8 * FS_STRIDE + 4];
    }
    __syncthreads();

    float m0 = -1e30f, m1 = -1e30f, l0 = 0.f, l1 = 0.f;
    float oacc[8][4] = {};

    for (int n0 = 0; n0 < PSEQ; n0 += 64) {
        // ---- load K and V tiles (64x64 each)
#pragma unroll
        for (int u = 0; u < 8; u++) {
            int idx = u * 128 + tid;
            int r = idx >> 4, c4 = idx & 15;
            float4 kv = *(const float4*)(K + (rowbase + n0 + r) * HID + colbase + c4 * 4);
            float4 vv = *(const float4*)(V + (rowbase + n0 + r) * HID + colbase + c4 * 4);
            *(uint4*)&KPs[r * FS_STRIDE + c4 * 4] =
                make_uint4(f2tf32(kv.x), f2tf32(kv.y), f2tf32(kv.z), f2tf32(kv.w));
            *(uint4*)&Vs[r * FS_STRIDE + c4 * 4] =
                make_uint4(f2tf32(vv.x), f2tf32(vv.y), f2tf32(vv.z), f2tf32(vv.w));
        }
        __syncthreads();

        // ---- S = Q K^T (warp's 16 q-rows x 64 kv)
        float sacc[8][4] = {};
#pragma unroll
        for (int ks = 0; ks < 8; ks++) {
#pragma unroll
            for (int nt = 0; nt < 8; nt++) {
                const uint32_t* p = &KPs[(nt * 8 + gid) * FS_STRIDE + ks * 8 + tig];
                MMA_TF32(sacc[nt], qf[ks], p[0], p[4]);
            }
        }

        // ---- online softmax (rows gid, gid+8 of warp's 16)
        float rmax0 = -1e30f, rmax1 = -1e30f;
#pragma unroll
        for (int nt = 0; nt < 8; nt++) {
            sacc[nt][0] *= 0.125f; sacc[nt][1] *= 0.125f;
            sacc[nt][2] *= 0.125f; sacc[nt][3] *= 0.125f;
            rmax0 = fmaxf(rmax0, fmaxf(sacc[nt][0], sacc[nt][1]));
            rmax1 = fmaxf(rmax1, fmaxf(sacc[nt][2], sacc[nt][3]));
        }
        rmax0 = fmaxf(rmax0, __shfl_xor_sync(0xffffffffu, rmax0, 1));
        rmax0 = fmaxf(rmax0, __shfl_xor_sync(0xffffffffu, rmax0, 2));
        rmax1 = fmaxf(rmax1, __shfl_xor_sync(0xffffffffu, rmax1, 1));
        rmax1 = fmaxf(rmax1, __shfl_xor_sync(0xffffffffu, rmax1, 2));
        float m0n = fmaxf(m0, rmax0);
        float m1n = fmaxf(m1, rmax1);
        float alpha0 = __expf(m0 - m0n);
        float alpha1 = __expf(m1 - m1n);
        float rs0 = 0.f, rs1 = 0.f;
#pragma unroll
        for (int nt = 0; nt < 8; nt++) {
            sacc[nt][0] = __expf(sacc[nt][0] - m0n);
            sacc[nt][1] = __expf(sacc[nt][1] - m0n);
            sacc[nt][2] = __expf(sacc[nt][2] - m1n);
            sacc[nt][3] = __expf(sacc[nt][3] - m1n);
            rs0 += sacc[nt][0] + sacc[nt][1];
            rs1 += sacc[nt][2] + sacc[nt][3];
        }
        rs0 += __shfl_xor_sync(0xffffffffu, rs0, 1);
        rs0 += __shfl_xor_sync(0xffffffffu, rs0, 2);
        rs1 += __shfl_xor_sync(0xffffffffu, rs1, 1);
        rs1 += __shfl_xor_sync(0xffffffffu, rs1, 2);
        l0 = l0 * alpha0 + rs0;
        l1 = l1 * alpha1 + rs1;
        m0 = m0n; m1 = m1n;
#pragma unroll
        for (int dt = 0; dt < 8; dt++) {
            oacc[dt][0] *= alpha0; oacc[dt][1] *= alpha0;
            oacc[dt][2] *= alpha1; oacc[dt][3] *= alpha1;
        }
        __syncthreads();   // everyone done reading KPs as K

        // ---- write P (64x64) into KPs
#pragma unroll
        for (int nt = 0; nt < 8; nt++) {
            uint32_t* p = &KPs[(wid * 16 + gid) * FS_STRIDE + nt * 8 + tig * 2];
            p[0] = f2tf32(sacc[nt][0]);
            p[1] = f2tf32(sacc[nt][1]);
            p[8 * FS_STRIDE + 0] = f2tf32(sacc[nt][2]);
            p[8 * FS_STRIDE + 1] = f2tf32(sacc[nt][3]);
        }
        __syncthreads();

        // ---- O += P @ V
#pragma unroll
        for (int ks = 0; ks < 8; ks++) {
            uint32_t pa[4];
            const uint32_t* pp = &KPs[(wid * 16 + gid) * FS_STRIDE + ks * 8 + tig];
            pa[0] = pp[0];
            pa[1] = pp[8 * FS_STRIDE];
            pa[2] = pp[4];
            pa[3] = pp[8 * FS_STRIDE + 4];
#pragma unroll
            for (int dt = 0; dt < 8; dt++) {
                const uint32_t* vp = &Vs[(ks * 8 + tig) * FS_STRIDE + dt * 8 + gid];
                MMA_TF32(oacc[dt], pa, vp[0], vp[4 * FS_STRIDE]);
            }
        }
        __syncthreads();   // before next tile overwrites KPs/Vs
    }

    // ---- epilogue
    float inv0 = 1.0f / l0;
    float inv1 = 1.0f / l1;
    size_t r0 = rowbase + q0 + wid * 16 + gid;
#pragma unroll
    for (int dt = 0; dt < 8; dt++) {
        int c = colbase + dt * 8 + tig * 2;
        float2 o0 = {oacc[dt][0] * inv0, oacc[dt][1] * inv0};
        float2 o1 = {oacc[dt][2] * inv1, oacc[dt][3] * inv1};
        *(float2*)(O + r0 * HID + c) = o0;
        *(float2*)(O + (r0 + 8) * HID + c) = o1;
    }
}

// ---------------------------------------------------------------------------
extern "C" void kernel_launch(void* const* d_in, const int* in_sizes, int n_in,
                              void* d_out, int out_size)
{
    const float* X  = (const float*)d_in[0];
    const float* Wq = (const float*)d_in[1];
    const float* bq = (const float*)d_in[2];
    const float* Wk = (const float*)d_in[3];
    const float* bk = (const float*)d_in[4];
    const float* Wv = (const float*)d_in[5];
    const float* bv = (const float*)d_in[6];
    const float* Wo = (const float*)d_in[7];
    const float* bo = (const float*)d_in[8];
    float* out = (float*)d_out;

    static float *pq = nullptr, *pk = nullptr, *pv = nullptr, *pctx = nullptr;
    if (!pq) {
        cudaGetSymbolAddress((void**)&pq, g_q);
        cudaGetSymbolAddress((void**)&pk, g_k);
        cudaGetSymbolAddress((void**)&pv, g_v);
        cudaGetSymbolAddress((void**)&pctx, g_ctx);
    }

    dim3 gproj(HID / 128, NROWS / 128);   // (6, 128)
    gemm_mma<<<gproj, 256>>>(X, Wq, bq, pq);
    gemm_mma<<<gproj, 256>>>(X, Wk, bk, pk);
    gemm_mma<<<gproj, 256>>>(X, Wv, bv, pv);

    dim3 gattn(PSEQ / 64, NH, NROWS / PSEQ);  // (8, 12, 32)
    flash_mma<<<gattn, 128>>>(pq, pk, pv, pctx);

    gemm_mma<<<gproj, 256>>>(pctx, Wo, bo, out);
}

// round 5
// speedup vs baseline: 3.6799x; 1.0211x over previous
#include <cuda_runtime.h>
#include <cstdint>

#define NROWS 16384   // B*M*P = 8*4*512
#define HID   768
#define NH    12
#define HS    64
#define PSEQ  512

// Scratch (allocation-free rule: __device__ globals)
__device__ float g_xtf[NROWS * HID];
__device__ float g_wtf[4 * HID * HID];
__device__ float g_q[NROWS * HID];
__device__ float g_k[NROWS * HID];
__device__ float g_v[NROWS * HID];
__device__ float g_ctx[NROWS * HID];

// ---------------------------------------------------------------------------
// helpers
// ---------------------------------------------------------------------------
__device__ __forceinline__ uint32_t f2tf32(float f) {
    uint32_t r;
    asm("cvt.rna.tf32.f32 %0, %1;" : "=r"(r) : "f"(f));
    return r;
}
__device__ __forceinline__ uint32_t smem_u32(const void* p) {
    uint32_t a;
    asm("{ .reg .u64 t; cvta.to.shared.u64 t, %1; cvt.u32.u64 %0, t; }" : "=r"(a) : "l"(p));
    return a;
}
#define CP16(dst_u32, src_ptr) \
    asm volatile("cp.async.cg.shared.global [%0], [%1], 16;" :: "r"(dst_u32), "l"(src_ptr) : "memory")
#define CP_COMMIT() asm volatile("cp.async.commit_group;" ::: "memory")
#define CP_WAIT(n)  asm volatile("cp.async.wait_group %0;" :: "n"(n) : "memory")

// D += A*B, m16n8k8 tf32 (row.col)
#define MMA_TF32(d, a, b0, b1) \
    asm volatile("mma.sync.aligned.m16n8k8.row.col.f32.tf32.tf32.f32 " \
        "{%0,%1,%2,%3}, {%4,%5,%6,%7}, {%8,%9}, {%0,%1,%2,%3};" \
        : "+f"((d)[0]), "+f"((d)[1]), "+f"((d)[2]), "+f"((d)[3]) \
        : "r"((a)[0]), "r"((a)[1]), "r"((a)[2]), "r"((a)[3]), "r"(b0), "r"(b1))

// ---------------------------------------------------------------------------
// Pre-round fp32 -> tf32-in-fp32 (vectorized). n4 = element count / 4.
// ---------------------------------------------------------------------------
__global__ __launch_bounds__(256) void round_tf32_k(
    const float* __restrict__ in, float* __restrict__ out, int n4)
{
    int i = blockIdx.x * 256 + threadIdx.x;
    if (i < n4) {
        float4 v = ((const float4*)in)[i];
        uint4 o = make_uint4(f2tf32(v.x), f2tf32(v.y), f2tf32(v.z), f2tf32(v.w));
        ((uint4*)out)[i] = o;
    }
}

// ===========================================================================
// GEMM: C[16384,768] = A @ W + bias  (A, W pre-rounded to tf32)
// tile 128x128x32, 256 threads = 8 warps (2x4), warp tile 64x32.
// 2-stage cp.async double-buffered pipeline; dynamic smem 70656 B.
// ===========================================================================
#define AS_STRIDE 36    // dwords; row = 144 B (16B-aligned)
#define BS_STRIDE 132   // dwords; row = 528 B (16B-aligned)
#define A_BUF (128 * AS_STRIDE)
#define B_BUF (32 * BS_STRIDE)
#define KITERS (HID / 32)   // 24
#define GEMM_SMEM ((2 * A_BUF + 2 * B_BUF) * 4)   // 70656 bytes

__global__ __launch_bounds__(256) void gemm_mma(
    const float* __restrict__ A, const float* __restrict__ W,
    const float* __restrict__ bias, float* __restrict__ C, int round_out)
{
    extern __shared__ __align__(16) uint32_t sm[];
    uint32_t* AsBase = sm;                 // [2][A_BUF]
    uint32_t* BsBase = sm + 2 * A_BUF;     // [2][B_BUF]
    const uint32_t as_addr = smem_u32(AsBase);
    const uint32_t bs_addr = smem_u32(BsBase);

    const int tid = threadIdx.x;
    const int wid = tid >> 5;
    const int lane = tid & 31;
    const int gid = lane >> 2;
    const int tig = lane & 3;
    const int wm = wid >> 2;
    const int wn = wid & 3;
    const int bm = blockIdx.y * 128;
    const int bn = blockIdx.x * 128;

    float acc[4][4][4] = {};

    // issue cp.asyncs for K-tile `it` into buffer it&1
    auto issue_tile = [&](int it) {
        const int k0 = it * 32;
        const uint32_t ad = as_addr + (uint32_t)((it & 1) * A_BUF * 4);
        const uint32_t bd = bs_addr + (uint32_t)((it & 1) * B_BUF * 4);
#pragma unroll
        for (int u = 0; u < 4; u++) {
            int idx = u * 256 + tid;
            int r = idx >> 3, c4 = idx & 7;
            CP16(ad + (uint32_t)(r * AS_STRIDE + c4 * 4) * 4,
                 A + (size_t)(bm + r) * HID + k0 + c4 * 4);
        }
#pragma unroll
        for (int u = 0; u < 4; u++) {
            int idx = u * 256 + tid;
            int kr = idx >> 5, nc = idx & 31;
            CP16(bd + (uint32_t)(kr * BS_STRIDE + nc * 4) * 4,
                 W + (size_t)(k0 + kr) * HID + bn + nc * 4);
        }
    };

    issue_tile(0);
    CP_COMMIT();

    for (int it = 0; it < KITERS; it++) {
        if (it + 1 < KITERS) {
            issue_tile(it + 1);
            CP_COMMIT();
            CP_WAIT(1);
        } else {
            CP_WAIT(0);
        }
        __syncthreads();

        const uint32_t* As = AsBase + (it & 1) * A_BUF;
        const uint32_t* Bs = BsBase + (it & 1) * B_BUF;
#pragma unroll
        for (int ks = 0; ks < 4; ks++) {
            uint32_t a[4][4];
#pragma unroll
            for (int mt = 0; mt < 4; mt++) {
                const uint32_t* p = &As[(wm * 64 + mt * 16 + gid) * AS_STRIDE + ks * 8 + tig];
                a[mt][0] = p[0];
                a[mt][1] = p[8 * AS_STRIDE];
                a[mt][2] = p[4];
                a[mt][3] = p[8 * AS_STRIDE + 4];
            }
#pragma unroll
            for (int nt = 0; nt < 4; nt++) {
                const uint32_t* p = &Bs[(ks * 8 + tig) * BS_STRIDE + wn * 32 + nt * 8 + gid];
                uint32_t b0 = p[0];
                uint32_t b1 = p[4 * BS_STRIDE];
#pragma unroll
                for (int mt = 0; mt < 4; mt++)
                    MMA_TF32(acc[mt][nt], a[mt], b0, b1);
            }
        }
        __syncthreads();
    }

    // epilogue
#pragma unroll
    for (int mt = 0; mt < 4; mt++) {
        int r0 = bm + wm * 64 + mt * 16 + gid;
#pragma unroll
        for (int nt = 0; nt < 4; nt++) {
            int c = bn + wn * 32 + nt * 8 + tig * 2;
            float b0 = bias[c], b1 = bias[c + 1];
            float o00 = acc[mt][nt][0] + b0, o01 = acc[mt][nt][1] + b1;
            float o10 = acc[mt][nt][2] + b0, o11 = acc[mt][nt][3] + b1;
            if (round_out) {
                o00 = __uint_as_float(f2tf32(o00));
                o01 = __uint_as_float(f2tf32(o01));
                o10 = __uint_as_float(f2tf32(o10));
                o11 = __uint_as_float(f2tf32(o11));
            }
            *(float2*)(C + (size_t)r0 * HID + c) = make_float2(o00, o01);
            *(float2*)(C + (size_t)(r0 + 8) * HID + c) = make_float2(o10, o11);
        }
    }
}

// ===========================================================================
// Flash attention with mma.sync tf32 (Q,K,V pre-rounded to tf32).
// Block = 128 thr (4 warps), q-tile 64 (warp owns 16 q-rows), KV tiles of 64.
// cp.async loads; softmax in registers; P round-trips through smem (aliased).
// ===========================================================================
#define FS_STRIDE 68   // dwords; row = 272 B (16B-aligned)

__global__ __launch_bounds__(128) void flash_mma(
    const float* __restrict__ Q, const float* __restrict__ K,
    const float* __restrict__ V, float* __restrict__ O)
{
    __shared__ __align__(16) uint32_t KPs[64 * FS_STRIDE];
    __shared__ __align__(16) uint32_t Vs[64 * FS_STRIDE];
    const uint32_t kb = smem_u32(KPs);
    const uint32_t vb = smem_u32(Vs);

    const int tid = threadIdx.x;
    const int wid = tid >> 5;
    const int lane = tid & 31;
    const int gid = lane >> 2;
    const int tig = lane & 3;
    const int q0 = blockIdx.x * 64;
    const int head = blockIdx.y;
    const int bmi = blockIdx.z;
    const size_t rowbase = (size_t)bmi * PSEQ;
    const int colbase = head * HS;

    // ---- load Q tile (64x64) via cp.async, lift to register fragments
#pragma unroll
    for (int u = 0; u < 8; u++) {
        int idx = u * 128 + tid;
        int r = idx >> 4, c4 = idx & 15;
        CP16(kb + (uint32_t)(r * FS_STRIDE + c4 * 4) * 4,
             Q + (rowbase + q0 + r) * HID + colbase + c4 * 4);
    }
    CP_COMMIT();
    CP_WAIT(0);
    __syncthreads();
    uint32_t qf[8][4];
#pragma unroll
    for (int ks = 0; ks < 8; ks++) {
        const uint32_t* p = &KPs[(wid * 16 + gid) * FS_STRIDE + ks * 8 + tig];
        qf[ks][0] = p[0];
        qf[ks][1] = p[8 * FS_STRIDE];
        qf[ks][2] = p[4];
        qf[ks][3] = p[8 * FS_STRIDE + 4];
    }
    __syncthreads();

    float m0 = -1e30f, m1 = -1e30f, l0 = 0.f, l1 = 0.f;
    float oacc[8][4] = {};

    for (int n0 = 0; n0 < PSEQ; n0 += 64) {
        // ---- load K and V tiles (64x64 each) via cp.async
#pragma unroll
        for (int u = 0; u < 8; u++) {
            int idx = u * 128 + tid;
            int r = idx >> 4, c4 = idx & 15;
            uint32_t off = (uint32_t)(r * FS_STRIDE + c4 * 4) * 4;
            const float* ksrc = K + (rowbase + n0 + r) * HID + colbase + c4 * 4;
            const float* vsrc = V + (rowbase + n0 + r) * HID + colbase + c4 * 4;
            CP16(kb + off, ksrc);
            CP16(vb + off, vsrc);
        }
        CP_COMMIT();
        CP_WAIT(0);
        __syncthreads();

        // ---- S = Q K^T (warp's 16 q-rows x 64 kv)
        float sacc[8][4] = {};
#pragma unroll
        for (int ks = 0; ks < 8; ks++) {
#pragma unroll
            for (int nt = 0; nt < 8; nt++) {
                const uint32_t* p = &KPs[(nt * 8 + gid) * FS_STRIDE + ks * 8 + tig];
                MMA_TF32(sacc[nt], qf[ks], p[0], p[4]);
            }
        }

        // ---- online softmax (rows gid, gid+8 of warp's 16)
        float rmax0 = -1e30f, rmax1 = -1e30f;
#pragma unroll
        for (int nt = 0; nt < 8; nt++) {
            sacc[nt][0] *= 0.125f; sacc[nt][1] *= 0.125f;
            sacc[nt][2] *= 0.125f; sacc[nt][3] *= 0.125f;
            rmax0 = fmaxf(rmax0, fmaxf(sacc[nt][0], sacc[nt][1]));
            rmax1 = fmaxf(rmax1, fmaxf(sacc[nt][2], sacc[nt][3]));
        }
        rmax0 = fmaxf(rmax0, __shfl_xor_sync(0xffffffffu, rmax0, 1));
        rmax0 = fmaxf(rmax0, __shfl_xor_sync(0xffffffffu, rmax0, 2));
        rmax1 = fmaxf(rmax1, __shfl_xor_sync(0xffffffffu, rmax1, 1));
        rmax1 = fmaxf(rmax1, __shfl_xor_sync(0xffffffffu, rmax1, 2));
        float m0n = fmaxf(m0, rmax0);
        float m1n = fmaxf(m1, rmax1);
        float alpha0 = __expf(m0 - m0n);
        float alpha1 = __expf(m1 - m1n);
        float rs0 = 0.f, rs1 = 0.f;
#pragma unroll
        for (int nt = 0; nt < 8; nt++) {
            sacc[nt][0] = __expf(sacc[nt][0] - m0n);
            sacc[nt][1] = __expf(sacc[nt][1] - m0n);
            sacc[nt][2] = __expf(sacc[nt][2] - m1n);
            sacc[nt][3] = __expf(sacc[nt][3] - m1n);
            rs0 += sacc[nt][0] + sacc[nt][1];
            rs1 += sacc[nt][2] + sacc[nt][3];
        }
        rs0 += __shfl_xor_sync(0xffffffffu, rs0, 1);
        rs0 += __shfl_xor_sync(0xffffffffu, rs0, 2);
        rs1 += __shfl_xor_sync(0xffffffffu, rs1, 1);
        rs1 += __shfl_xor_sync(0xffffffffu, rs1, 2);
        l0 = l0 * alpha0 + rs0;
        l1 = l1 * alpha1 + rs1;
        m0 = m0n; m1 = m1n;
#pragma unroll
        for (int dt = 0; dt < 8; dt++) {
            oacc[dt][0] *= alpha0; oacc[dt][1] *= alpha0;
            oacc[dt][2] *= alpha1; oacc[dt][3] *= alpha1;
        }
        __syncthreads();   // everyone done reading KPs as K

        // ---- write P (64x64) into KPs
#pragma unroll
        for (int nt = 0; nt < 8; nt++) {
            uint32_t* p = &KPs[(wid * 16 + gid) * FS_STRIDE + nt * 8 + tig * 2];
            p[0] = f2tf32(sacc[nt][0]);
            p[1] = f2tf32(sacc[nt][1]);
            p[8 * FS_STRIDE + 0] = f2tf32(sacc[nt][2]);
            p[8 * FS_STRIDE + 1] = f2tf32(sacc[nt][3]);
        }
        __syncthreads();

        // ---- O += P @ V
#pragma unroll
        for (int ks = 0; ks < 8; ks++) {
            uint32_t pa[4];
            const uint32_t* pp = &KPs[(wid * 16 + gid) * FS_STRIDE + ks * 8 + tig];
            pa[0] = pp[0];
            pa[1] = pp[8 * FS_STRIDE];
            pa[2] = pp[4];
            pa[3] = pp[8 * FS_STRIDE + 4];
#pragma unroll
            for (int dt = 0; dt < 8; dt++) {
                const uint32_t* vp = &Vs[(ks * 8 + tig) * FS_STRIDE + dt * 8 + gid];
                MMA_TF32(oacc[dt], pa, vp[0], vp[4 * FS_STRIDE]);
            }
        }
        __syncthreads();   // before next tile overwrites KPs/Vs
    }

    // ---- epilogue: write ctx pre-rounded to tf32 (feeds out-proj cp.async path)
    float inv0 = 1.0f / l0;
    float inv1 = 1.0f / l1;
    size_t r0 = rowbase + q0 + wid * 16 + gid;
#pragma unroll
    for (int dt = 0; dt < 8; dt++) {
        int c = colbase + dt * 8 + tig * 2;
        uint32_t o00 = f2tf32(oacc[dt][0] * inv0);
        uint32_t o01 = f2tf32(oacc[dt][1] * inv0);
        uint32_t o10 = f2tf32(oacc[dt][2] * inv1);
        uint32_t o11 = f2tf32(oacc[dt][3] * inv1);
        *(float2*)(O + r0 * HID + c) =
            make_float2(__uint_as_float(o00), __uint_as_float(o01));
        *(float2*)(O + (r0 + 8) * HID + c) =
            make_float2(__uint_as_float(o10), __uint_as_float(o11));
    }
}

// ---------------------------------------------------------------------------
extern "C" void kernel_launch(void* const* d_in, const int* in_sizes, int n_in,
                              void* d_out, int out_size)
{
    const float* X  = (const float*)d_in[0];
    const float* Wq = (const float*)d_in[1];
    const float* bq = (const float*)d_in[2];
    const float* Wk = (const float*)d_in[3];
    const float* bk = (const float*)d_in[4];
    const float* Wv = (const float*)d_in[5];
    const float* bv = (const float*)d_in[6];
    const float* Wo = (const float*)d_in[7];
    const float* bo = (const float*)d_in[8];
    float* out = (float*)d_out;

    static float *pxtf = nullptr, *pwtf = nullptr,
                 *pq = nullptr, *pk = nullptr, *pv = nullptr, *pctx = nullptr;
    if (!pq) {
        cudaGetSymbolAddress((void**)&pxtf, g_xtf);
        cudaGetSymbolAddress((void**)&pwtf, g_wtf);
        cudaGetSymbolAddress((void**)&pq, g_q);
        cudaGetSymbolAddress((void**)&pk, g_k);
        cudaGetSymbolAddress((void**)&pv, g_v);
        cudaGetSymbolAddress((void**)&pctx, g_ctx);
        cudaFuncSetAttribute(gemm_mma, cudaFuncAttributeMaxDynamicSharedMemorySize, GEMM_SMEM);
    }

    // pre-round X and all weights to tf32
    const int n4x = NROWS * HID / 4;          // 3145728
    const int n4w = HID * HID / 4;            // 147456
    round_tf32_k<<<(n4x + 255) / 256, 256>>>(X, pxtf, n4x);
    round_tf32_k<<<(n4w + 255) / 256, 256>>>(Wq, pwtf + 0 * HID * HID, n4w);
    round_tf32_k<<<(n4w + 255) / 256, 256>>>(Wk, pwtf + 1 * HID * HID, n4w);
    round_tf32_k<<<(n4w + 255) / 256, 256>>>(Wv, pwtf + 2 * HID * HID, n4w);
    round_tf32_k<<<(n4w + 255) / 256, 256>>>(Wo, pwtf + 3 * HID * HID, n4w);

    dim3 gproj(HID / 128, NROWS / 128);   // (6, 128)
    gemm_mma<<<gproj, 256, GEMM_SMEM>>>(pxtf, pwtf + 0 * HID * HID, bq, pq, 1);
    gemm_mma<<<gproj, 256, GEMM_SMEM>>>(pxtf, pwtf + 1 * HID * HID, bk, pk, 1);
    gemm_mma<<<gproj, 256, GEMM_SMEM>>>(pxtf, pwtf + 2 * HID * HID, bv, pv, 1);

    dim3 gattn(PSEQ / 64, NH, NROWS / PSEQ);  // (8, 12, 32)
    flash_mma<<<gattn, 128>>>(pq, pk, pv, pctx);

    gemm_mma<<<gproj, 256, GEMM_SMEM>>>(pctx, pwtf + 3 * HID * HID, bo, out, 0);
}